// round 15
// baseline (speedup 1.0000x reference)
#include <cuda_runtime.h>
#include <cuda_fp16.h>
#include <cstdint>

#define BATCH 4
#define SEQ   2048
#define DM    768
#define NH    12
#define TOK   (BATCH*SEQ)   // 8192

// ---------------------------------------------------------------------------
// Scratch (uint4 for guaranteed 16B alignment; elements are fp16)
// ---------------------------------------------------------------------------
__device__ uint4 g_Xhi4 [(size_t)TOK*DM/8],  g_Xlo4 [(size_t)TOK*DM/8];
__device__ uint4 g_Wthi4[(size_t)3*NH*64*DM/8], g_Wtlo4[(size_t)3*NH*64*DM/8]; // [mat*NH+h][n][m]
__device__ uint4 g_WOt4[(size_t)DM*DM/8];                                      // [d][n] single
__device__ uint4 g_Qhi4 [(size_t)TOK*DM/8], g_Qlo4 [(size_t)TOK*DM/8];  // [b,h,s,d] (pre-scaled by CSC)
__device__ uint4 g_Khi4 [(size_t)TOK*DM/8], g_Klo4 [(size_t)TOK*DM/8];  // [b,h,s,d]
__device__ uint4 g_Vt4  [(size_t)TOK*DM/8];                             // [b,h,d,s] single
__device__ uint4 g_MHhi4[(size_t)TOK*DM/8], g_MHlo4[(size_t)TOK*DM/8];  // [t, h*64+v]

#define HF(p) ((__half*)(p))

// ---------------------------------------------------------------------------
// Helpers
// ---------------------------------------------------------------------------
__device__ __forceinline__ uint32_t smem_u32(const void* p){
    uint32_t a;
    asm("{ .reg .u64 t; cvta.to.shared.u64 t, %1; cvt.u32.u64 %0, t; }" : "=r"(a) : "l"(p));
    return a;
}
__device__ __forceinline__ void mma_f16(float* d, const uint32_t* a,
                                        uint32_t b0, uint32_t b1){
    asm volatile("mma.sync.aligned.m16n8k16.row.col.f32.f16.f16.f32 "
        "{%0,%1,%2,%3}, {%4,%5,%6,%7}, {%8,%9}, {%0,%1,%2,%3};"
        : "+f"(d[0]), "+f"(d[1]), "+f"(d[2]), "+f"(d[3])
        : "r"(a[0]), "r"(a[1]), "r"(a[2]), "r"(a[3]), "r"(b0), "r"(b1));
}
__device__ __forceinline__ void ldsm4(uint32_t addr, uint32_t* r){
    asm volatile("ldmatrix.sync.aligned.m8n8.x4.shared.b16 {%0,%1,%2,%3}, [%4];"
        : "=r"(r[0]), "=r"(r[1]), "=r"(r[2]), "=r"(r[3]) : "r"(addr));
}
__device__ __forceinline__ void cpa16(uint32_t saddr, const void* g){
    asm volatile("cp.async.cg.shared.global [%0], [%1], 16;" :: "r"(saddr), "l"(g));
}
#define CP_COMMIT() asm volatile("cp.async.commit_group;" ::: "memory")
#define CP_WAIT0()  asm volatile("cp.async.wait_group 0;" ::: "memory")
#define CP_WAIT1()  asm volatile("cp.async.wait_group 1;" ::: "memory")

__device__ __forceinline__ uint32_t pack2(float v0, float v1){
    __half2 h = __floats2half2_rn(v0, v1);
    return *(uint32_t*)&h;
}
__device__ __forceinline__ void pack_hilo(float v0, float v1, uint32_t& hi, uint32_t& lo){
    __half2 hp = __floats2half2_rn(v0, v1);
    float l0 = v0 - __half2float(__low2half(hp));
    float l1 = v1 - __half2float(__high2half(hp));
    __half2 lp = __floats2half2_rn(l0, l1);
    hi = *(uint32_t*)&hp; lo = *(uint32_t*)&lp;
}
__device__ __forceinline__ float exp2a(float t){
    float r;
    asm("ex2.approx.ftz.f32 %0, %1;" : "=f"(r) : "f"(t));
    return r;
}

// ---------------------------------------------------------------------------
// Prep: fp32 -> fp16 hi/lo (+ weight transposes)
// ---------------------------------------------------------------------------
__global__ __launch_bounds__(256) void prep_x(const float* __restrict__ X){
    int i0 = (blockIdx.x * 256 + threadIdx.x) * 8;
    #pragma unroll
    for (int k = 0; k < 8; k++){
        int i = i0 + k;
        float v = X[i];
        __half h = __float2half_rn(v);
        HF(g_Xhi4)[i] = h;
        HF(g_Xlo4)[i] = __float2half_rn(v - __half2float(h));
    }
}

__global__ __launch_bounds__(256) void prep_wqkv(const float* __restrict__ WQ,
                                                 const float* __restrict__ WK,
                                                 const float* __restrict__ WV){
    __shared__ float tile[64][65];
    int x = blockIdx.x;               // mat*12 + h
    int mt = blockIdx.y;              // m tile (12)
    int mat = x / NH, h = x % NH;
    const float* src = (mat == 0 ? WQ : mat == 1 ? WK : WV) + (size_t)h * DM * 64;
    int tid = threadIdx.x;
    #pragma unroll
    for (int i = 0; i < 16; i++){
        int idx = tid + i * 256;
        int r = idx >> 6, c = idx & 63;
        tile[r][c] = src[(size_t)(mt * 64 + r) * 64 + c];
    }
    __syncthreads();
    #pragma unroll
    for (int i = 0; i < 16; i++){
        int idx = tid + i * 256;
        int n = idx >> 6, mc = idx & 63;
        float v = tile[mc][n];
        __half hh = __float2half_rn(v);
        size_t o = ((size_t)x * 64 + n) * DM + mt * 64 + mc;
        HF(g_Wthi4)[o] = hh;
        HF(g_Wtlo4)[o] = __float2half_rn(v - __half2float(hh));
    }
}

__global__ __launch_bounds__(256) void prep_wo(const float* __restrict__ WO){
    __shared__ float tile[64][65];
    int nt = blockIdx.x, dt = blockIdx.y;
    int tid = threadIdx.x;
    #pragma unroll
    for (int i = 0; i < 16; i++){
        int idx = tid + i * 256;
        int r = idx >> 6, c = idx & 63;
        tile[r][c] = WO[(size_t)(nt * 64 + r) * DM + dt * 64 + c];
    }
    __syncthreads();
    #pragma unroll
    for (int i = 0; i < 16; i++){
        int idx = tid + i * 256;
        int dr = idx >> 6, nc = idx & 63;
        size_t o = (size_t)(dt * 64 + dr) * DM + nt * 64 + nc;
        HF(g_WOt4)[o] = __float2half_rn(tile[nc][dr]);
    }
}

// ---------------------------------------------------------------------------
// GEMM: 128x128 tile, K chunks of 48 (16 chunks), 512 threads = 16 warps
// (4m x 4n), warp tile 32x32, cp.async 2-stage, ldmatrix. Stride 56hw.
// ---------------------------------------------------------------------------
#define GSA 56
#define GTILE 14336
#define GEMM_SMEM (2*4*GTILE)   // 114688 (3-term); 2-term uses 2*3*GTILE

template<bool THREE>
__device__ __forceinline__ void gemm_cpa_chunk(
    const __half* GA_h, const __half* GA_l,
    const __half* GB_h, const __half* GB_l,
    int arow0, int brow0, int ch, uint32_t sdst, int tid)
{
    // 128 rows x 48hw chunk = 128 x 6 16B-copies = 768 units
    #pragma unroll
    for (int k = 0; k < 2; k++){
        int c = tid + k * 512;
        if (c < 768){
            int row = c / 6, q = c - row * 6;
            size_t ga = (size_t)(arow0 + row) * DM + ch * 48 + q * 8;
            size_t gb = (size_t)(brow0 + row) * DM + ch * 48 + q * 8;
            uint32_t so = (uint32_t)((row * GSA + q * 8) * 2);
            cpa16(sdst           + so, GA_h + ga);
            cpa16(sdst +   GTILE + so, GA_l + ga);
            cpa16(sdst + 2*GTILE + so, GB_h + gb);
            if (THREE) cpa16(sdst + 3*GTILE + so, GB_l + gb);
        }
    }
}

template<bool THREE>
__device__ __forceinline__ void gemm_core(
    const __half* GA_h, const __half* GA_l,
    const __half* GB_h, const __half* GB_l,
    int arow0, int brow0, uint32_t sb,
    int tid, int wm, int wn, int lane,
    float acc[2][4][4])
{
    const int STG = (THREE ? 4 : 3) * GTILE;
    const int a_r = lane & 15, a_c = (lane & 16) >> 1;
    const int b_r = (lane & 7) + ((lane & 16) >> 1), b_c = lane & 8;

    gemm_cpa_chunk<THREE>(GA_h, GA_l, GB_h, GB_l, arow0, brow0, 0, sb, tid);
    CP_COMMIT();

    for (int ch = 0; ch < 16; ch++){
        CP_WAIT0();
        __syncthreads();
        if (ch + 1 < 16){
            gemm_cpa_chunk<THREE>(GA_h, GA_l, GB_h, GB_l, arow0, brow0, ch + 1,
                                  sb + ((ch + 1) & 1) * STG, tid);
            CP_COMMIT();
        }
        const uint32_t st = sb + (ch & 1) * STG;
        #pragma unroll
        for (int k0 = 0; k0 < 48; k0 += 16){
            uint32_t ah[2][4], al[2][4];
            #pragma unroll
            for (int mt = 0; mt < 2; mt++){
                uint32_t ad = st + ((wm * 32 + mt * 16 + a_r) * GSA + k0 + a_c) * 2;
                ldsm4(ad, ah[mt]);
                ldsm4(ad + GTILE, al[mt]);
            }
            #pragma unroll
            for (int p = 0; p < 2; p++){
                uint32_t bd = st + 2 * GTILE +
                              ((wn * 32 + p * 16 + b_r) * GSA + k0 + b_c) * 2;
                uint32_t bh4[4];
                ldsm4(bd, bh4);
                if (THREE){
                    uint32_t bl4[4];
                    ldsm4(bd + GTILE, bl4);
                    #pragma unroll
                    for (int mt = 0; mt < 2; mt++){
                        mma_f16(acc[mt][2*p],   ah[mt], bh4[0], bh4[1]);
                        mma_f16(acc[mt][2*p],   ah[mt], bl4[0], bl4[1]);
                        mma_f16(acc[mt][2*p],   al[mt], bh4[0], bh4[1]);
                        mma_f16(acc[mt][2*p+1], ah[mt], bh4[2], bh4[3]);
                        mma_f16(acc[mt][2*p+1], ah[mt], bl4[2], bl4[3]);
                        mma_f16(acc[mt][2*p+1], al[mt], bh4[2], bh4[3]);
                    }
                } else {
                    #pragma unroll
                    for (int mt = 0; mt < 2; mt++){
                        mma_f16(acc[mt][2*p],   ah[mt], bh4[0], bh4[1]);
                        mma_f16(acc[mt][2*p],   al[mt], bh4[0], bh4[1]);
                        mma_f16(acc[mt][2*p+1], ah[mt], bh4[2], bh4[3]);
                        mma_f16(acc[mt][2*p+1], al[mt], bh4[2], bh4[3]);
                    }
                }
            }
        }
    }
}

// QKV projection. Q: 3-term, scaled by CSC at output. K: 3-term. V: 2-term.
__global__ __launch_bounds__(512, 2) void gemm_qkv(){
    extern __shared__ __align__(16) char smem[];
    const uint32_t sb = smem_u32(smem);
    const int tid = threadIdx.x, w = tid >> 5, lane = tid & 31;
    const int wm = w & 3, wn = w >> 2;
    const int r = lane >> 2, c2 = (lane & 3) * 2;
    const int t0 = blockIdx.x * 128;
    const int j = blockIdx.y;
    const int mat = j / 6, h0 = (j % 6) * 2;
    const int brow0 = (mat * NH + h0) * 64;
    const float oscale = (mat == 0) ? 0.125f * 1.4426950408889634f : 1.0f;

    float acc[2][4][4] = {};
    if (mat < 2)
        gemm_core<true >(HF(g_Xhi4), HF(g_Xlo4), HF(g_Wthi4), HF(g_Wtlo4),
                         t0, brow0, sb, tid, wm, wn, lane, acc);
    else
        gemm_core<false>(HF(g_Xhi4), HF(g_Xlo4), HF(g_Wthi4), HF(g_Wtlo4),
                         t0, brow0, sb, tid, wm, wn, lane, acc);

    #pragma unroll
    for (int mt = 0; mt < 2; mt++){
        #pragma unroll
        for (int hf = 0; hf < 2; hf++){
            int srow = t0 + wm * 32 + mt * 16 + r + hf * 8;
            int bb = srow >> 11, s = srow & 2047;
            if (mat < 2){
                uint32_t* DH = (uint32_t*)(mat == 0 ? g_Qhi4 : g_Khi4);
                uint32_t* DL = (uint32_t*)(mat == 0 ? g_Qlo4 : g_Klo4);
                #pragma unroll
                for (int nt = 0; nt < 4; nt++){
                    int cl = wn * 32 + nt * 8 + c2;      // 0..127
                    int hh = h0 + (cl >> 6), d = cl & 63;
                    size_t base = ((size_t)(bb * NH + hh) * SEQ + s) * 32;
                    uint32_t hi, lo;
                    pack_hilo(acc[mt][nt][hf*2] * oscale, acc[mt][nt][hf*2+1] * oscale, hi, lo);
                    DH[base + (d >> 1)] = hi;
                    DL[base + (d >> 1)] = lo;
                }
            } else {
                __half* VT = HF(g_Vt4);
                #pragma unroll
                for (int nt = 0; nt < 4; nt++){
                    #pragma unroll
                    for (int j2 = 0; j2 < 2; j2++){
                        int cl = wn * 32 + nt * 8 + c2 + j2;
                        int hh = h0 + (cl >> 6), d = cl & 63;
                        size_t o = ((size_t)(bb * NH + hh) * 64 + d) * SEQ + s;
                        VT[o] = __float2half_rn(acc[mt][nt][hf*2+j2]);
                    }
                }
            }
        }
    }
}

// Output projection (2-term)
__global__ __launch_bounds__(512, 2) void gemm_oproj(float* __restrict__ out){
    extern __shared__ __align__(16) char smem[];
    const uint32_t sb = smem_u32(smem);
    const int tid = threadIdx.x, w = tid >> 5, lane = tid & 31;
    const int wm = w & 3, wn = w >> 2;
    const int r = lane >> 2, c2 = (lane & 3) * 2;
    const int t0 = blockIdx.x * 128;
    const int d0 = blockIdx.y * 128;

    float acc[2][4][4] = {};
    gemm_core<false>(HF(g_MHhi4), HF(g_MHlo4), HF(g_WOt4), HF(g_WOt4),
                     t0, d0, sb, tid, wm, wn, lane, acc);

    #pragma unroll
    for (int mt = 0; mt < 2; mt++){
        #pragma unroll
        for (int hf = 0; hf < 2; hf++){
            int srow = t0 + wm * 32 + mt * 16 + r + hf * 8;
            #pragma unroll
            for (int nt = 0; nt < 4; nt++){
                int dcol = d0 + wn * 32 + nt * 8 + c2;
                float2 v = make_float2(acc[mt][nt][hf*2], acc[mt][nt][hf*2+1]);
                *(float2*)(out + (size_t)srow * DM + dcol) = v;
            }
        }
    }
}

// ---------------------------------------------------------------------------
// Flash attention: 128-q tile, kv processed in PAIRS of 64-tiles (count always
// even). 8 warps as 8m x 1n. Q (pre-scaled) hi+lo in registers. 2 pair-stages:
// one wait + one syncthreads per PAIR. smem 110592 -> 2 CTAs/SM (221KB<=228KB).
// ---------------------------------------------------------------------------
#define ASA     72
#define AKTILE  9216
#define ASUBSTG (3*AKTILE)                 // 27648 (one kv tile: Kh,Kl,V)
#define APAIRSTG (2*ASUBSTG)               // 55296
#define ATTN_SMEM (2*APAIRSTG)             // 110592

__device__ __forceinline__ void attn_cpa_kv(
    const __half* KH, const __half* KL, const __half* VT,
    int bh_idx, int jj, uint32_t sdst, int lrow, int lq)
{
    size_t gk = ((size_t)bh_idx * SEQ + jj * 64 + lrow) * 64 + lq * 16;
    size_t gv = ((size_t)(bh_idx * 64 + lrow)) * SEQ + jj * 64 + lq * 16;
    uint32_t so = (uint32_t)((lrow * ASA + lq * 16) * 2);
    cpa16(sdst            + so, KH + gk); cpa16(sdst            + so + 16, KH + gk + 8);
    cpa16(sdst +   AKTILE + so, KL + gk); cpa16(sdst +   AKTILE + so + 16, KL + gk + 8);
    cpa16(sdst + 2*AKTILE + so, VT + gv); cpa16(sdst + 2*AKTILE + so + 16, VT + gv + 8);
}

__global__ __launch_bounds__(256, 2) void attn_kernel(){
    extern __shared__ __align__(16) char smem[];
    const uint32_t sb = smem_u32(smem);

    const int tid = threadIdx.x, w = tid >> 5, lane = tid & 31;
    const int r = lane >> 2, c2 = (lane & 3) * 2;
    const int a_r = lane & 15, a_c = (lane & 16) >> 1;
    const int b_r = (lane & 7) + ((lane & 16) >> 1), b_c = lane & 8;

    const int qt = 15 - blockIdx.x;   // heavy tiles first
    const int pr = blockIdx.y;
    const int b = pr / NH, h = pr % NH;
    const int bh_idx = b * NH + h;
    const int npair = qt + 1;         // kv tiles = 2*npair (always even)

    const __half* QH = HF(g_Qhi4);
    const __half* QL = HF(g_Qlo4);
    const __half* KH = HF(g_Khi4);
    const __half* KL = HF(g_Klo4);
    const __half* VT = HF(g_Vt4);

    const int lrowQ = tid >> 1, lhQ = tid & 1;
    const int lrowK = tid >> 2, lqK = tid & 3;
    const uint32_t st1 = sb + APAIRSTG;

    // prologue: g0 = Qh->st1, Ql->st1+18432 ; g1 = pair0 -> stage0
    {
        size_t gq = ((size_t)bh_idx * SEQ + qt * 128 + lrowQ) * 64 + lhQ * 32;
        uint32_t so = (uint32_t)((lrowQ * ASA + lhQ * 32) * 2);
        #pragma unroll
        for (int i = 0; i < 4; i++){
            cpa16(st1         + so + i * 16, QH + gq + i * 8);
            cpa16(st1 + 18432 + so + i * 16, QL + gq + i * 8);
        }
        CP_COMMIT();
        attn_cpa_kv(KH, KL, VT, bh_idx, 0, sb, lrowK, lqK);
        attn_cpa_kv(KH, KL, VT, bh_idx, 1, sb + ASUBSTG, lrowK, lqK);
        CP_COMMIT();
    }

    // Q fragments -> registers (loop-invariant)
    uint32_t qh[4][4], ql[4][4];
    CP_WAIT1();
    __syncthreads();
    #pragma unroll
    for (int kc = 0; kc < 4; kc++){
        uint32_t qo = ((w * 16 + a_r) * ASA + kc * 16 + a_c) * 2;
        ldsm4(st1 + qo, qh[kc]);
        ldsm4(st1 + 18432 + qo, ql[kc]);
    }

    float O[8][4] = {};
    float m_i[2] = {-1e30f, -1e30f};
    float l_i[2] = {0.f, 0.f};    // per-thread partials

    for (int pp = 0; pp < npair; pp++){
        CP_WAIT0();          // pair pp landed (only outstanding group)
        __syncthreads();     // visible to all warps; prior stage fully consumed
        if (pp + 1 < npair){
            uint32_t nst = sb + ((pp + 1) & 1) * APAIRSTG;
            attn_cpa_kv(KH, KL, VT, bh_idx, 2*(pp+1),     nst,           lrowK, lqK);
            attn_cpa_kv(KH, KL, VT, bh_idx, 2*(pp+1) + 1, nst + ASUBSTG, lrowK, lqK);
            CP_COMMIT();
        }
        const uint32_t stage = sb + (pp & 1) * APAIRSTG;

        #pragma unroll
        for (int sub = 0; sub < 2; sub++){
            const uint32_t stk = stage + sub * ASUBSTG;
            const int jj = 2 * pp + sub;

            // ---- S = Q K^T (3-term); logits already in log2 domain ----
            float sacc[8][4] = {};
            #pragma unroll
            for (int kc = 0; kc < 4; kc++){
                const int k0 = kc * 16;
                #pragma unroll
                for (int p = 0; p < 4; p++){
                    uint32_t ka = stk + ((p * 16 + b_r) * ASA + k0 + b_c) * 2;
                    uint32_t kh4[4], kl4[4];
                    ldsm4(ka, kh4);
                    ldsm4(ka + AKTILE, kl4);
                    mma_f16(sacc[2*p],   qh[kc], kh4[0], kh4[1]);
                    mma_f16(sacc[2*p],   qh[kc], kl4[0], kl4[1]);
                    mma_f16(sacc[2*p],   ql[kc], kh4[0], kh4[1]);
                    mma_f16(sacc[2*p+1], qh[kc], kh4[2], kh4[3]);
                    mma_f16(sacc[2*p+1], qh[kc], kl4[2], kl4[3]);
                    mma_f16(sacc[2*p+1], ql[kc], kh4[2], kh4[3]);
                }
            }

            // ---- mask (diagonal tiles only) + quad row max ----
            const bool domask = (jj >= 2 * qt);
            float mn[2];
            #pragma unroll
            for (int hf = 0; hf < 2; hf++){
                float mx = -1e30f;
                if (domask){
                    int qrow = qt * 128 + w * 16 + hf * 8 + r;
                    #pragma unroll
                    for (int nt = 0; nt < 8; nt++){
                        #pragma unroll
                        for (int j2 = 0; j2 < 2; j2++){
                            int col = jj * 64 + nt * 8 + c2 + j2;
                            float v = sacc[nt][hf*2+j2];
                            if (col > qrow) v = -1e30f;
                            sacc[nt][hf*2+j2] = v;
                            mx = fmaxf(mx, v);
                        }
                    }
                } else {
                    #pragma unroll
                    for (int nt = 0; nt < 8; nt++){
                        mx = fmaxf(mx, fmaxf(sacc[nt][hf*2], sacc[nt][hf*2+1]));
                    }
                }
                mx = fmaxf(mx, __shfl_xor_sync(0xffffffffu, mx, 1));
                mx = fmaxf(mx, __shfl_xor_sync(0xffffffffu, mx, 2));
                mn[hf] = fmaxf(m_i[hf], mx);
            }

            // ---- warp-uniform rescale (skipped when no row max changed) ----
            if (__any_sync(0xffffffffu, (mn[0] > m_i[0]) | (mn[1] > m_i[1]))){
                #pragma unroll
                for (int hf = 0; hf < 2; hf++){
                    float alpha = exp2a(m_i[hf] - mn[hf]);
                    m_i[hf] = mn[hf];
                    l_i[hf] *= alpha;
                    #pragma unroll
                    for (int nt = 0; nt < 8; nt++){
                        O[nt][hf*2]   *= alpha;
                        O[nt][hf*2+1] *= alpha;
                    }
                }
            }

            // ---- exp + per-thread l partial ----
            #pragma unroll
            for (int hf = 0; hf < 2; hf++){
                float rs = 0.f;
                #pragma unroll
                for (int nt = 0; nt < 8; nt++){
                    #pragma unroll
                    for (int j2 = 0; j2 < 2; j2++){
                        float p = exp2a(sacc[nt][hf*2+j2] - m_i[hf]);
                        sacc[nt][hf*2+j2] = p;
                        rs += p;
                    }
                }
                l_i[hf] += rs;
            }

            // ---- PV (1-term): pack P per kc2 then consume immediately ----
            #pragma unroll
            for (int kc2 = 0; kc2 < 4; kc2++){
                uint32_t pa4[4];
                pa4[0] = pack2(sacc[2*kc2][0],   sacc[2*kc2][1]);
                pa4[1] = pack2(sacc[2*kc2][2],   sacc[2*kc2][3]);
                pa4[2] = pack2(sacc[2*kc2+1][0], sacc[2*kc2+1][1]);
                pa4[3] = pack2(sacc[2*kc2+1][2], sacc[2*kc2+1][3]);
                #pragma unroll
                for (int p = 0; p < 4; p++){
                    uint32_t va = stk + 2 * AKTILE + ((p * 16 + b_r) * ASA + kc2 * 16 + b_c) * 2;
                    uint32_t vh4[4];
                    ldsm4(va, vh4);
                    mma_f16(O[2*p],   pa4, vh4[0], vh4[1]);
                    mma_f16(O[2*p+1], pa4, vh4[2], vh4[3]);
                }
            }
        }
    }

    // ---- reduce l across quad, normalize, write MH hi/lo ----
    {
        uint32_t* MHH = (uint32_t*)g_MHhi4;
        uint32_t* MHL = (uint32_t*)g_MHlo4;
        #pragma unroll
        for (int hf = 0; hf < 2; hf++){
            float lt = l_i[hf];
            lt += __shfl_xor_sync(0xffffffffu, lt, 1);
            lt += __shfl_xor_sync(0xffffffffu, lt, 2);
            float linv = 1.f / lt;
            int row = w * 16 + hf * 8 + r;
            size_t t = (size_t)b * SEQ + qt * 128 + row;
            #pragma unroll
            for (int nt = 0; nt < 8; nt++){
                uint32_t hi, lo;
                pack_hilo(O[nt][hf*2] * linv, O[nt][hf*2+1] * linv, hi, lo);
                size_t col = h * 64 + nt * 8 + c2;
                MHH[(t * DM + col) >> 1] = hi;
                MHL[(t * DM + col) >> 1] = lo;
            }
        }
    }
}

// ---------------------------------------------------------------------------
extern "C" void kernel_launch(void* const* d_in, const int* in_sizes, int n_in,
                              void* d_out, int out_size)
{
    const float* residual = (const float*)d_in[0];
    const float* W_Q = (const float*)d_in[1];
    const float* W_K = (const float*)d_in[2];
    const float* W_V = (const float*)d_in[3];
    const float* W_O = (const float*)d_in[4];
    float* out = (float*)d_out;

    cudaFuncSetAttribute(gemm_qkv,   cudaFuncAttributeMaxDynamicSharedMemorySize, GEMM_SMEM);
    cudaFuncSetAttribute(gemm_oproj, cudaFuncAttributeMaxDynamicSharedMemorySize, GEMM_SMEM);
    cudaFuncSetAttribute(attn_kernel, cudaFuncAttributeMaxDynamicSharedMemorySize, ATTN_SMEM);

    prep_x<<<TOK * DM / (256 * 8), 256>>>(residual);
    prep_wqkv<<<dim3(3 * NH, 12), 256>>>(W_Q, W_K, W_V);
    prep_wo<<<dim3(12, 12), 256>>>(W_O);

    gemm_qkv<<<dim3(64, 18), 512, GEMM_SMEM>>>();
    attn_kernel<<<dim3(16, BATCH * NH), 256, ATTN_SMEM>>>();
    gemm_oproj<<<dim3(64, 6), 512, 2*3*GTILE>>>(out);
}

// round 16
// speedup vs baseline: 1.1080x; 1.1080x over previous
#include <cuda_runtime.h>
#include <cuda_fp16.h>
#include <cstdint>

#define BATCH 4
#define SEQ   2048
#define DM    768
#define NH    12
#define TOK   (BATCH*SEQ)   // 8192

// ---------------------------------------------------------------------------
// Scratch (uint4 for guaranteed 16B alignment; elements are fp16)
// ---------------------------------------------------------------------------
__device__ uint4 g_Xhi4 [(size_t)TOK*DM/8],  g_Xlo4 [(size_t)TOK*DM/8];
__device__ uint4 g_Wthi4[(size_t)3*NH*64*DM/8], g_Wtlo4[(size_t)3*NH*64*DM/8]; // [mat*NH+h][n][m]
__device__ uint4 g_WOt4[(size_t)DM*DM/8];                                      // [d][n] single
__device__ uint4 g_Qhi4 [(size_t)TOK*DM/8], g_Qlo4 [(size_t)TOK*DM/8];  // [b,h,s,d] (pre-scaled by CSC)
__device__ uint4 g_Khi4 [(size_t)TOK*DM/8], g_Klo4 [(size_t)TOK*DM/8];  // [b,h,s,d]
__device__ uint4 g_Vt4  [(size_t)TOK*DM/8];                             // [b,h,d,s] single
__device__ uint4 g_MH4  [(size_t)TOK*DM/8];                             // [t, h*64+v] single

#define HF(p) ((__half*)(p))

// ---------------------------------------------------------------------------
// Helpers
// ---------------------------------------------------------------------------
__device__ __forceinline__ uint32_t smem_u32(const void* p){
    uint32_t a;
    asm("{ .reg .u64 t; cvta.to.shared.u64 t, %1; cvt.u32.u64 %0, t; }" : "=r"(a) : "l"(p));
    return a;
}
__device__ __forceinline__ void mma_f16(float* d, const uint32_t* a,
                                        uint32_t b0, uint32_t b1){
    asm volatile("mma.sync.aligned.m16n8k16.row.col.f32.f16.f16.f32 "
        "{%0,%1,%2,%3}, {%4,%5,%6,%7}, {%8,%9}, {%0,%1,%2,%3};"
        : "+f"(d[0]), "+f"(d[1]), "+f"(d[2]), "+f"(d[3])
        : "r"(a[0]), "r"(a[1]), "r"(a[2]), "r"(a[3]), "r"(b0), "r"(b1));
}
__device__ __forceinline__ void ldsm4(uint32_t addr, uint32_t* r){
    asm volatile("ldmatrix.sync.aligned.m8n8.x4.shared.b16 {%0,%1,%2,%3}, [%4];"
        : "=r"(r[0]), "=r"(r[1]), "=r"(r[2]), "=r"(r[3]) : "r"(addr));
}
__device__ __forceinline__ void cpa16(uint32_t saddr, const void* g){
    asm volatile("cp.async.cg.shared.global [%0], [%1], 16;" :: "r"(saddr), "l"(g));
}
#define CP_COMMIT() asm volatile("cp.async.commit_group;" ::: "memory")
#define CP_WAIT0()  asm volatile("cp.async.wait_group 0;" ::: "memory")
#define CP_WAIT1()  asm volatile("cp.async.wait_group 1;" ::: "memory")

__device__ __forceinline__ uint32_t pack2(float v0, float v1){
    __half2 h = __floats2half2_rn(v0, v1);
    return *(uint32_t*)&h;
}
__device__ __forceinline__ void pack_hilo(float v0, float v1, uint32_t& hi, uint32_t& lo){
    __half2 hp = __floats2half2_rn(v0, v1);
    float l0 = v0 - __half2float(__low2half(hp));
    float l1 = v1 - __half2float(__high2half(hp));
    __half2 lp = __floats2half2_rn(l0, l1);
    hi = *(uint32_t*)&hp; lo = *(uint32_t*)&lp;
}
__device__ __forceinline__ float exp2a(float t){
    float r;
    asm("ex2.approx.ftz.f32 %0, %1;" : "=f"(r) : "f"(t));
    return r;
}

// ---------------------------------------------------------------------------
// Prep: fp32 -> fp16 hi/lo (+ weight transposes)
// ---------------------------------------------------------------------------
__global__ __launch_bounds__(256) void prep_x(const float* __restrict__ X){
    int i0 = (blockIdx.x * 256 + threadIdx.x) * 8;
    #pragma unroll
    for (int k = 0; k < 8; k++){
        int i = i0 + k;
        float v = X[i];
        __half h = __float2half_rn(v);
        HF(g_Xhi4)[i] = h;
        HF(g_Xlo4)[i] = __float2half_rn(v - __half2float(h));
    }
}

__global__ __launch_bounds__(256) void prep_wqkv(const float* __restrict__ WQ,
                                                 const float* __restrict__ WK,
                                                 const float* __restrict__ WV){
    __shared__ float tile[64][65];
    int x = blockIdx.x;               // mat*12 + h
    int mt = blockIdx.y;              // m tile (12)
    int mat = x / NH, h = x % NH;
    const float* src = (mat == 0 ? WQ : mat == 1 ? WK : WV) + (size_t)h * DM * 64;
    int tid = threadIdx.x;
    #pragma unroll
    for (int i = 0; i < 16; i++){
        int idx = tid + i * 256;
        int r = idx >> 6, c = idx & 63;
        tile[r][c] = src[(size_t)(mt * 64 + r) * 64 + c];
    }
    __syncthreads();
    #pragma unroll
    for (int i = 0; i < 16; i++){
        int idx = tid + i * 256;
        int n = idx >> 6, mc = idx & 63;
        float v = tile[mc][n];
        __half hh = __float2half_rn(v);
        size_t o = ((size_t)x * 64 + n) * DM + mt * 64 + mc;
        HF(g_Wthi4)[o] = hh;
        HF(g_Wtlo4)[o] = __float2half_rn(v - __half2float(hh));
    }
}

__global__ __launch_bounds__(256) void prep_wo(const float* __restrict__ WO){
    __shared__ float tile[64][65];
    int nt = blockIdx.x, dt = blockIdx.y;
    int tid = threadIdx.x;
    #pragma unroll
    for (int i = 0; i < 16; i++){
        int idx = tid + i * 256;
        int r = idx >> 6, c = idx & 63;
        tile[r][c] = WO[(size_t)(nt * 64 + r) * DM + dt * 64 + c];
    }
    __syncthreads();
    #pragma unroll
    for (int i = 0; i < 16; i++){
        int idx = tid + i * 256;
        int dr = idx >> 6, nc = idx & 63;
        size_t o = (size_t)(dt * 64 + dr) * DM + nt * 64 + nc;
        HF(g_WOt4)[o] = __float2half_rn(tile[nc][dr]);
    }
}

// ---------------------------------------------------------------------------
// GEMM: 128x128 tile, K chunks of 48 (16 chunks), 512 threads = 16 warps
// (4m x 4n), warp tile 32x32, cp.async 2-stage, ldmatrix. Stride 56hw.
// TERMS: 3 = Ah*Bh+Ah*Bl+Al*Bh; 2 = Ah*B+Al*B; 1 = Ah*Bh.
// Stage tiles: Ah [,Al if T>=2], Bh [,Bl if T==3].
// ---------------------------------------------------------------------------
#define GSA 56
#define GTILE 14336
#define GEMM_SMEM (2*4*GTILE)   // 114688 (3-term max)

template<int TERMS>
__device__ __forceinline__ void gemm_cpa_chunk(
    const __half* GA_h, const __half* GA_l,
    const __half* GB_h, const __half* GB_l,
    int arow0, int brow0, int ch, uint32_t sdst, int tid)
{
    const uint32_t BOFF = (TERMS >= 2 ? 2 : 1) * GTILE;
    // 128 rows x 48hw chunk = 128 x 6 16B-copies = 768 units
    #pragma unroll
    for (int k = 0; k < 2; k++){
        int c = tid + k * 512;
        if (c < 768){
            int row = c / 6, q = c - row * 6;
            size_t ga = (size_t)(arow0 + row) * DM + ch * 48 + q * 8;
            size_t gb = (size_t)(brow0 + row) * DM + ch * 48 + q * 8;
            uint32_t so = (uint32_t)((row * GSA + q * 8) * 2);
            cpa16(sdst + so, GA_h + ga);
            if (TERMS >= 2) cpa16(sdst + GTILE + so, GA_l + ga);
            cpa16(sdst + BOFF + so, GB_h + gb);
            if (TERMS == 3) cpa16(sdst + 3*GTILE + so, GB_l + gb);
        }
    }
}

template<int TERMS>
__device__ __forceinline__ void gemm_core(
    const __half* GA_h, const __half* GA_l,
    const __half* GB_h, const __half* GB_l,
    int arow0, int brow0, uint32_t sb,
    int tid, int wm, int wn, int lane,
    float acc[2][4][4])
{
    const int STG = (TERMS + 1) * GTILE;
    const uint32_t BOFF = (TERMS >= 2 ? 2 : 1) * GTILE;
    const int a_r = lane & 15, a_c = (lane & 16) >> 1;
    const int b_r = (lane & 7) + ((lane & 16) >> 1), b_c = lane & 8;

    gemm_cpa_chunk<TERMS>(GA_h, GA_l, GB_h, GB_l, arow0, brow0, 0, sb, tid);
    CP_COMMIT();

    for (int ch = 0; ch < 16; ch++){
        CP_WAIT0();
        __syncthreads();
        if (ch + 1 < 16){
            gemm_cpa_chunk<TERMS>(GA_h, GA_l, GB_h, GB_l, arow0, brow0, ch + 1,
                                  sb + ((ch + 1) & 1) * STG, tid);
            CP_COMMIT();
        }
        const uint32_t st = sb + (ch & 1) * STG;
        #pragma unroll
        for (int k0 = 0; k0 < 48; k0 += 16){
            uint32_t ah[2][4], al[2][4];
            #pragma unroll
            for (int mt = 0; mt < 2; mt++){
                uint32_t ad = st + ((wm * 32 + mt * 16 + a_r) * GSA + k0 + a_c) * 2;
                ldsm4(ad, ah[mt]);
                if (TERMS >= 2) ldsm4(ad + GTILE, al[mt]);
            }
            #pragma unroll
            for (int p = 0; p < 2; p++){
                uint32_t bd = st + BOFF +
                              ((wn * 32 + p * 16 + b_r) * GSA + k0 + b_c) * 2;
                uint32_t bh4[4];
                ldsm4(bd, bh4);
                if (TERMS == 3){
                    uint32_t bl4[4];
                    ldsm4(bd + GTILE, bl4);
                    #pragma unroll
                    for (int mt = 0; mt < 2; mt++){
                        mma_f16(acc[mt][2*p],   ah[mt], bh4[0], bh4[1]);
                        mma_f16(acc[mt][2*p],   ah[mt], bl4[0], bl4[1]);
                        mma_f16(acc[mt][2*p],   al[mt], bh4[0], bh4[1]);
                        mma_f16(acc[mt][2*p+1], ah[mt], bh4[2], bh4[3]);
                        mma_f16(acc[mt][2*p+1], ah[mt], bl4[2], bl4[3]);
                        mma_f16(acc[mt][2*p+1], al[mt], bh4[2], bh4[3]);
                    }
                } else if (TERMS == 2){
                    #pragma unroll
                    for (int mt = 0; mt < 2; mt++){
                        mma_f16(acc[mt][2*p],   ah[mt], bh4[0], bh4[1]);
                        mma_f16(acc[mt][2*p],   al[mt], bh4[0], bh4[1]);
                        mma_f16(acc[mt][2*p+1], ah[mt], bh4[2], bh4[3]);
                        mma_f16(acc[mt][2*p+1], al[mt], bh4[2], bh4[3]);
                    }
                } else {
                    #pragma unroll
                    for (int mt = 0; mt < 2; mt++){
                        mma_f16(acc[mt][2*p],   ah[mt], bh4[0], bh4[1]);
                        mma_f16(acc[mt][2*p+1], ah[mt], bh4[2], bh4[3]);
                    }
                }
            }
        }
    }
}

// QKV projection. Q: 3-term, scaled by CSC at output. K: 3-term. V: 1-term.
__global__ __launch_bounds__(512, 2) void gemm_qkv(){
    extern __shared__ __align__(16) char smem[];
    const uint32_t sb = smem_u32(smem);
    const int tid = threadIdx.x, w = tid >> 5, lane = tid & 31;
    const int wm = w & 3, wn = w >> 2;
    const int r = lane >> 2, c2 = (lane & 3) * 2;
    const int t0 = blockIdx.x * 128;
    const int j = blockIdx.y;
    const int mat = j / 6, h0 = (j % 6) * 2;
    const int brow0 = (mat * NH + h0) * 64;
    const float oscale = (mat == 0) ? 0.125f * 1.4426950408889634f : 1.0f;

    float acc[2][4][4] = {};
    if (mat < 2)
        gemm_core<3>(HF(g_Xhi4), HF(g_Xlo4), HF(g_Wthi4), HF(g_Wtlo4),
                     t0, brow0, sb, tid, wm, wn, lane, acc);
    else
        gemm_core<1>(HF(g_Xhi4), HF(g_Xlo4), HF(g_Wthi4), HF(g_Wtlo4),
                     t0, brow0, sb, tid, wm, wn, lane, acc);

    #pragma unroll
    for (int mt = 0; mt < 2; mt++){
        #pragma unroll
        for (int hf = 0; hf < 2; hf++){
            int srow = t0 + wm * 32 + mt * 16 + r + hf * 8;
            int bb = srow >> 11, s = srow & 2047;
            if (mat < 2){
                uint32_t* DH = (uint32_t*)(mat == 0 ? g_Qhi4 : g_Khi4);
                uint32_t* DL = (uint32_t*)(mat == 0 ? g_Qlo4 : g_Klo4);
                #pragma unroll
                for (int nt = 0; nt < 4; nt++){
                    int cl = wn * 32 + nt * 8 + c2;      // 0..127
                    int hh = h0 + (cl >> 6), d = cl & 63;
                    size_t base = ((size_t)(bb * NH + hh) * SEQ + s) * 32;
                    uint32_t hi, lo;
                    pack_hilo(acc[mt][nt][hf*2] * oscale, acc[mt][nt][hf*2+1] * oscale, hi, lo);
                    DH[base + (d >> 1)] = hi;
                    DL[base + (d >> 1)] = lo;
                }
            } else {
                __half* VT = HF(g_Vt4);
                #pragma unroll
                for (int nt = 0; nt < 4; nt++){
                    #pragma unroll
                    for (int j2 = 0; j2 < 2; j2++){
                        int cl = wn * 32 + nt * 8 + c2 + j2;
                        int hh = h0 + (cl >> 6), d = cl & 63;
                        size_t o = ((size_t)(bb * NH + hh) * 64 + d) * SEQ + s;
                        VT[o] = __float2half_rn(acc[mt][nt][hf*2+j2]);
                    }
                }
            }
        }
    }
}

// Output projection (1-term: MH single x WO single)
__global__ __launch_bounds__(512, 2) void gemm_oproj(float* __restrict__ out){
    extern __shared__ __align__(16) char smem[];
    const uint32_t sb = smem_u32(smem);
    const int tid = threadIdx.x, w = tid >> 5, lane = tid & 31;
    const int wm = w & 3, wn = w >> 2;
    const int r = lane >> 2, c2 = (lane & 3) * 2;
    const int t0 = blockIdx.x * 128;
    const int d0 = blockIdx.y * 128;

    float acc[2][4][4] = {};
    gemm_core<1>(HF(g_MH4), HF(g_MH4), HF(g_WOt4), HF(g_WOt4),
                 t0, d0, sb, tid, wm, wn, lane, acc);

    #pragma unroll
    for (int mt = 0; mt < 2; mt++){
        #pragma unroll
        for (int hf = 0; hf < 2; hf++){
            int srow = t0 + wm * 32 + mt * 16 + r + hf * 8;
            #pragma unroll
            for (int nt = 0; nt < 4; nt++){
                int dcol = d0 + wn * 32 + nt * 8 + c2;
                float2 v = make_float2(acc[mt][nt][hf*2], acc[mt][nt][hf*2+1]);
                *(float2*)(out + (size_t)srow * DM + dcol) = v;
            }
        }
    }
}

// ---------------------------------------------------------------------------
// Flash attention: 128-q tile, 64-kv tile, 8 warps as 8m x 1n.
// Q (pre-scaled) hi+lo in registers; 3 KV stages; smem 82944 -> 2 CTAs/SM.
// MH written as SINGLE fp16.
// ---------------------------------------------------------------------------
#define ASA    72
#define AKTILE 9216
#define AKVSTG (3*AKTILE)                  // 27648
#define ATTN_SMEM (3*AKVSTG)               // 82944

__device__ __forceinline__ void attn_cpa_kv(
    const __half* KH, const __half* KL, const __half* VT,
    int bh_idx, int jj, uint32_t sdst, int lrow, int lq)
{
    size_t gk = ((size_t)bh_idx * SEQ + jj * 64 + lrow) * 64 + lq * 16;
    size_t gv = ((size_t)(bh_idx * 64 + lrow)) * SEQ + jj * 64 + lq * 16;
    uint32_t so = (uint32_t)((lrow * ASA + lq * 16) * 2);
    cpa16(sdst            + so, KH + gk); cpa16(sdst            + so + 16, KH + gk + 8);
    cpa16(sdst +   AKTILE + so, KL + gk); cpa16(sdst +   AKTILE + so + 16, KL + gk + 8);
    cpa16(sdst + 2*AKTILE + so, VT + gv); cpa16(sdst + 2*AKTILE + so + 16, VT + gv + 8);
}

__global__ __launch_bounds__(256, 2) void attn_kernel(){
    extern __shared__ __align__(16) char smem[];
    const uint32_t sb = smem_u32(smem);

    const int tid = threadIdx.x, w = tid >> 5, lane = tid & 31;
    const int r = lane >> 2, c2 = (lane & 3) * 2;
    const int a_r = lane & 15, a_c = (lane & 16) >> 1;
    const int b_r = (lane & 7) + ((lane & 16) >> 1), b_c = lane & 8;

    const int qt = 15 - blockIdx.x;   // heavy tiles first
    const int pr = blockIdx.y;
    const int b = pr / NH, h = pr % NH;
    const int bh_idx = b * NH + h;
    const int jmax = 2 * qt + 1;      // >= 1

    const __half* QH = HF(g_Qhi4);
    const __half* QL = HF(g_Qlo4);
    const __half* KH = HF(g_Khi4);
    const __half* KL = HF(g_Klo4);
    const __half* VT = HF(g_Vt4);

    const int lrowQ = tid >> 1, lhQ = tid & 1;
    const int lrowK = tid >> 2, lqK = tid & 3;
    const uint32_t stage1 = sb + AKVSTG;
    const uint32_t stage2 = sb + 2 * AKVSTG;

    // prologue: g0 = Qh->stage1, Ql->stage2 ; g1 = kv0->stage0
    {
        size_t gq = ((size_t)bh_idx * SEQ + qt * 128 + lrowQ) * 64 + lhQ * 32;
        uint32_t so = (uint32_t)((lrowQ * ASA + lhQ * 32) * 2);
        #pragma unroll
        for (int i = 0; i < 4; i++){
            cpa16(stage1 + so + i * 16, QH + gq + i * 8);
            cpa16(stage2 + so + i * 16, QL + gq + i * 8);
        }
        CP_COMMIT();
        attn_cpa_kv(KH, KL, VT, bh_idx, 0, sb, lrowK, lqK);
        CP_COMMIT();
    }

    // Q fragments -> registers (loop-invariant)
    uint32_t qh[4][4], ql[4][4];
    CP_WAIT1();
    __syncthreads();
    #pragma unroll
    for (int kc = 0; kc < 4; kc++){
        uint32_t qo = ((w * 16 + a_r) * ASA + kc * 16 + a_c) * 2;
        ldsm4(stage1 + qo, qh[kc]);
        ldsm4(stage2 + qo, ql[kc]);
    }
    __syncthreads();   // all warps done reading stage1/stage2
    attn_cpa_kv(KH, KL, VT, bh_idx, 1, stage1, lrowK, lqK);   // kv1 (jmax>=1 always)
    CP_COMMIT();

    float O[8][4] = {};
    float m_i[2] = {-1e30f, -1e30f};
    float l_i[2] = {0.f, 0.f};    // per-thread partials

    for (int jj = 0; jj <= jmax; jj++){
        if (jj < jmax) CP_WAIT1(); else CP_WAIT0();
        __syncthreads();
        if (jj + 2 <= jmax){
            attn_cpa_kv(KH, KL, VT, bh_idx, jj + 2,
                        sb + ((jj + 2) % 3) * AKVSTG, lrowK, lqK);
            CP_COMMIT();
        }
        const uint32_t stk = sb + (jj % 3) * AKVSTG;

        // ---- S = Q K^T (3-term); logits already in log2 domain ----
        float sacc[8][4] = {};
        #pragma unroll
        for (int kc = 0; kc < 4; kc++){
            const int k0 = kc * 16;
            #pragma unroll
            for (int p = 0; p < 4; p++){
                uint32_t ka = stk + ((p * 16 + b_r) * ASA + k0 + b_c) * 2;
                uint32_t kh4[4], kl4[4];
                ldsm4(ka, kh4);
                ldsm4(ka + AKTILE, kl4);
                mma_f16(sacc[2*p],   qh[kc], kh4[0], kh4[1]);
                mma_f16(sacc[2*p],   qh[kc], kl4[0], kl4[1]);
                mma_f16(sacc[2*p],   ql[kc], kh4[0], kh4[1]);
                mma_f16(sacc[2*p+1], qh[kc], kh4[2], kh4[3]);
                mma_f16(sacc[2*p+1], qh[kc], kl4[2], kl4[3]);
                mma_f16(sacc[2*p+1], ql[kc], kh4[2], kh4[3]);
            }
        }

        // ---- mask (diagonal tiles only) + quad row max ----
        const bool domask = (jj >= 2 * qt);
        float mn[2];
        #pragma unroll
        for (int hf = 0; hf < 2; hf++){
            float mx = -1e30f;
            if (domask){
                int qrow = qt * 128 + w * 16 + hf * 8 + r;
                #pragma unroll
                for (int nt = 0; nt < 8; nt++){
                    #pragma unroll
                    for (int j2 = 0; j2 < 2; j2++){
                        int col = jj * 64 + nt * 8 + c2 + j2;
                        float v = sacc[nt][hf*2+j2];
                        if (col > qrow) v = -1e30f;
                        sacc[nt][hf*2+j2] = v;
                        mx = fmaxf(mx, v);
                    }
                }
            } else {
                #pragma unroll
                for (int nt = 0; nt < 8; nt++){
                    mx = fmaxf(mx, fmaxf(sacc[nt][hf*2], sacc[nt][hf*2+1]));
                }
            }
            mx = fmaxf(mx, __shfl_xor_sync(0xffffffffu, mx, 1));
            mx = fmaxf(mx, __shfl_xor_sync(0xffffffffu, mx, 2));
            mn[hf] = fmaxf(m_i[hf], mx);
        }

        // ---- warp-uniform rescale (skipped when no row max changed) ----
        if (__any_sync(0xffffffffu, (mn[0] > m_i[0]) | (mn[1] > m_i[1]))){
            #pragma unroll
            for (int hf = 0; hf < 2; hf++){
                float alpha = exp2a(m_i[hf] - mn[hf]);
                m_i[hf] = mn[hf];
                l_i[hf] *= alpha;
                #pragma unroll
                for (int nt = 0; nt < 8; nt++){
                    O[nt][hf*2]   *= alpha;
                    O[nt][hf*2+1] *= alpha;
                }
            }
        }

        // ---- exp + per-thread l partial ----
        #pragma unroll
        for (int hf = 0; hf < 2; hf++){
            float rs = 0.f;
            #pragma unroll
            for (int nt = 0; nt < 8; nt++){
                #pragma unroll
                for (int j2 = 0; j2 < 2; j2++){
                    float p = exp2a(sacc[nt][hf*2+j2] - m_i[hf]);
                    sacc[nt][hf*2+j2] = p;
                    rs += p;
                }
            }
            l_i[hf] += rs;
        }

        // ---- PV (1-term): pack P per kc2 then consume immediately ----
        #pragma unroll
        for (int kc2 = 0; kc2 < 4; kc2++){
            uint32_t pa4[4];
            pa4[0] = pack2(sacc[2*kc2][0],   sacc[2*kc2][1]);
            pa4[1] = pack2(sacc[2*kc2][2],   sacc[2*kc2][3]);
            pa4[2] = pack2(sacc[2*kc2+1][0], sacc[2*kc2+1][1]);
            pa4[3] = pack2(sacc[2*kc2+1][2], sacc[2*kc2+1][3]);
            #pragma unroll
            for (int p = 0; p < 4; p++){
                uint32_t va = stk + 2 * AKTILE + ((p * 16 + b_r) * ASA + kc2 * 16 + b_c) * 2;
                uint32_t vh4[4];
                ldsm4(va, vh4);
                mma_f16(O[2*p],   pa4, vh4[0], vh4[1]);
                mma_f16(O[2*p+1], pa4, vh4[2], vh4[3]);
            }
        }
    }

    // ---- reduce l across quad, normalize, write MH (single fp16) ----
    {
        uint32_t* MHH = (uint32_t*)g_MH4;
        #pragma unroll
        for (int hf = 0; hf < 2; hf++){
            float lt = l_i[hf];
            lt += __shfl_xor_sync(0xffffffffu, lt, 1);
            lt += __shfl_xor_sync(0xffffffffu, lt, 2);
            float linv = 1.f / lt;
            int row = w * 16 + hf * 8 + r;
            size_t t = (size_t)b * SEQ + qt * 128 + row;
            #pragma unroll
            for (int nt = 0; nt < 8; nt++){
                size_t col = h * 64 + nt * 8 + c2;
                MHH[(t * DM + col) >> 1] = pack2(O[nt][hf*2] * linv, O[nt][hf*2+1] * linv);
            }
        }
    }
}

// ---------------------------------------------------------------------------
extern "C" void kernel_launch(void* const* d_in, const int* in_sizes, int n_in,
                              void* d_out, int out_size)
{
    const float* residual = (const float*)d_in[0];
    const float* W_Q = (const float*)d_in[1];
    const float* W_K = (const float*)d_in[2];
    const float* W_V = (const float*)d_in[3];
    const float* W_O = (const float*)d_in[4];
    float* out = (float*)d_out;

    cudaFuncSetAttribute(gemm_qkv,   cudaFuncAttributeMaxDynamicSharedMemorySize, GEMM_SMEM);
    cudaFuncSetAttribute(gemm_oproj, cudaFuncAttributeMaxDynamicSharedMemorySize, GEMM_SMEM);
    cudaFuncSetAttribute(attn_kernel, cudaFuncAttributeMaxDynamicSharedMemorySize, ATTN_SMEM);

    prep_x<<<TOK * DM / (256 * 8), 256>>>(residual);
    prep_wqkv<<<dim3(3 * NH, 12), 256>>>(W_Q, W_K, W_V);
    prep_wo<<<dim3(12, 12), 256>>>(W_O);

    gemm_qkv<<<dim3(64, 18), 512, GEMM_SMEM>>>();
    attn_kernel<<<dim3(16, BATCH * NH), 256, ATTN_SMEM>>>();
    gemm_oproj<<<dim3(64, 6), 512, 2*2*GTILE>>>(out);
}